// round 13
// baseline (speedup 1.0000x reference)
#include <cuda_runtime.h>
#include <cuda_bf16.h>
#include <cstdint>
#include <math.h>

// AttentiveRouter: N=32768 tokens, H=2048, H2=1024, E=8, top-2
#define N_TOK  32768
#define H_DIM  2048
#define H2_DIM 1024
#define E_DIM  8
#define GAP_DELTA 2e-3f
#define MAX_FLAG 4096
#define WSPLIT_BLOCKS 264
#define PATCH_BATCH 8

// ---------------- scratch (static device globals) ----------------
__device__ __nv_bfloat16 g_ahi[(size_t)N_TOK * H_DIM];   // 134 MB
__device__ __nv_bfloat16 g_alo[(size_t)N_TOK * H_DIM];   // 134 MB
__device__ __nv_bfloat16 g_whi[(size_t)H2_DIM * H_DIM];  // 4 MB
__device__ __nv_bfloat16 g_wlo[(size_t)H2_DIM * H_DIM];  // 4 MB
__device__ float g_lpart[8][N_TOK][E_DIM];               // per-bn partial logits, 8 MB
__device__ float g_mu[N_TOK];
__device__ float g_rs[N_TOK];
__device__ float g_psum[(N_TOK / 256) * E_DIM];
__device__ int   g_flagged[MAX_FLAG];
__device__ int   g_count;

__device__ __forceinline__ float gelu_exact(float v) {
    return 0.5f * v * (1.0f + erff(v * 0.70710678118654752440f));
}

// ---------------- K1: fused LayerNorm+split (rows) AND w1 split (tail blocks) ----------------
__global__ __launch_bounds__(256)
void prep(const float* __restrict__ x, const float* __restrict__ lnw,
          const float* __restrict__ lnb, const float* __restrict__ w1) {
    if ((int)blockIdx.x >= N_TOK) {
        // ---- w1 hi/lo split (grid-stride over WSPLIT_BLOCKS tail blocks) ----
        int wb = blockIdx.x - N_TOK;
        if (wb == 0 && threadIdx.x == 0) g_count = 0;
        const float4* src = (const float4*)w1;
        __nv_bfloat162* hi2 = (__nv_bfloat162*)g_whi;
        __nv_bfloat162* lo2 = (__nv_bfloat162*)g_wlo;
        int total = H2_DIM * H_DIM / 4;
        for (int i = wb * 256 + threadIdx.x; i < total; i += WSPLIT_BLOCKS * 256) {
            float4 v = src[i];
            __nv_bfloat162 h0 = __floats2bfloat162_rn(v.x, v.y);
            __nv_bfloat162 h1 = __floats2bfloat162_rn(v.z, v.w);
            __nv_bfloat162 l0 = __floats2bfloat162_rn(v.x - __bfloat162float(h0.x),
                                                      v.y - __bfloat162float(h0.y));
            __nv_bfloat162 l1 = __floats2bfloat162_rn(v.z - __bfloat162float(h1.x),
                                                      v.w - __bfloat162float(h1.y));
            hi2[i * 2 + 0] = h0; hi2[i * 2 + 1] = h1;
            lo2[i * 2 + 0] = l0; lo2[i * 2 + 1] = l1;
        }
        return;
    }

    // ---- LayerNorm stats + bf16 hi/lo split for one token row ----
    int row = blockIdx.x;
    const float4* xr = (const float4*)(x + (size_t)row * H_DIM);
    float4 v0 = xr[threadIdx.x];
    float4 v1 = xr[threadIdx.x + 256];
    float s  = v0.x + v0.y + v0.z + v0.w + v1.x + v1.y + v1.z + v1.w;
    float s2 = v0.x*v0.x + v0.y*v0.y + v0.z*v0.z + v0.w*v0.w
             + v1.x*v1.x + v1.y*v1.y + v1.z*v1.z + v1.w*v1.w;
    #pragma unroll
    for (int o = 16; o; o >>= 1) {
        s  += __shfl_xor_sync(0xffffffffu, s, o);
        s2 += __shfl_xor_sync(0xffffffffu, s2, o);
    }
    __shared__ float sh[8], sh2[8], smu, srs;
    int w = threadIdx.x >> 5, l = threadIdx.x & 31;
    if (l == 0) { sh[w] = s; sh2[w] = s2; }
    __syncthreads();
    if (threadIdx.x == 0) {
        float ts = 0.f, ts2 = 0.f;
        #pragma unroll
        for (int i = 0; i < 8; i++) { ts += sh[i]; ts2 += sh2[i]; }
        float mu  = ts / (float)H_DIM;
        float var = ts2 / (float)H_DIM - mu * mu;
        smu = mu; srs = rsqrtf(var + 1e-5f);
        g_mu[row] = mu; g_rs[row] = srs;
    }
    __syncthreads();
    float mu = smu, rs = srs;

    const float4* wr = (const float4*)lnw;
    const float4* br = (const float4*)lnb;
    __nv_bfloat162* hi2 = (__nv_bfloat162*)(g_ahi + (size_t)row * H_DIM);
    __nv_bfloat162* lo2 = (__nv_bfloat162*)(g_alo + (size_t)row * H_DIM);

    #pragma unroll
    for (int half = 0; half < 2; half++) {
        int qi = threadIdx.x + half * 256;
        float4 xv = half ? v1 : v0;
        float4 wv = wr[qi];
        float4 bv = br[qi];
        float o0 = (xv.x - mu) * rs * wv.x + bv.x;
        float o1 = (xv.y - mu) * rs * wv.y + bv.y;
        float o2 = (xv.z - mu) * rs * wv.z + bv.z;
        float o3 = (xv.w - mu) * rs * wv.w + bv.w;
        __nv_bfloat162 h0 = __floats2bfloat162_rn(o0, o1);
        __nv_bfloat162 h1 = __floats2bfloat162_rn(o2, o3);
        __nv_bfloat162 l0 = __floats2bfloat162_rn(o0 - __bfloat162float(h0.x),
                                                  o1 - __bfloat162float(h0.y));
        __nv_bfloat162 l1 = __floats2bfloat162_rn(o2 - __bfloat162float(h1.x),
                                                  o3 - __bfloat162float(h1.y));
        hi2[qi * 2 + 0] = h0; hi2[qi * 2 + 1] = h1;
        lo2[qi * 2 + 0] = l0; lo2[qi * 2 + 1] = l1;
    }
}

// ---------------- K2: mma.sync bf16x3 GEMM1 + fused bias/GELU/GEMM2-partial ----------------
// (R7-proven layout: 80B-padded smem rows, 2-stage cp.async pipeline)
#define BM 128
#define BN 128
#define BK 32
#define ROWB 80                        // padded smem row bytes (32 bf16 = 64B data)
#define BUF_BYTES (128 * ROWB)         // 10240 per operand buffer
#define STAGE_BYTES (4 * BUF_BYTES)    // Ahi | Alo | Bhi | Blo
#define GSMEM (2 * STAGE_BYTES)        // 81920 -> 2 CTAs/SM

extern __shared__ __align__(128) char dsm[];

__device__ __forceinline__ uint32_t smem_u32(const void* p) {
    uint32_t a;
    asm("{ .reg .u64 t; cvta.to.shared.u64 t, %1; cvt.u32.u64 %0, t; }" : "=r"(a) : "l"(p));
    return a;
}
#define CP16(dst, src) \
    asm volatile("cp.async.cg.shared.global [%0], [%1], 16;" :: "r"(dst), "l"(src))
#define CP_COMMIT() asm volatile("cp.async.commit_group;" ::: "memory")
#define CP_WAIT1()  asm volatile("cp.async.wait_group 1;" ::: "memory")

#define LDSM4(r, addr)                                                        \
    asm volatile("ldmatrix.sync.aligned.m8n8.x4.shared.b16 {%0,%1,%2,%3}, [%4];" \
        : "=r"((r)[0]), "=r"((r)[1]), "=r"((r)[2]), "=r"((r)[3]) : "r"(addr))

#define MMA16816(d, a, b0, b1)                                                \
    asm volatile("mma.sync.aligned.m16n8k16.row.col.f32.bf16.bf16.f32 "       \
        "{%0,%1,%2,%3},{%4,%5,%6,%7},{%8,%9},{%0,%1,%2,%3};"                  \
        : "+f"((d)[0]), "+f"((d)[1]), "+f"((d)[2]), "+f"((d)[3])              \
        : "r"((a)[0]), "r"((a)[1]), "r"((a)[2]), "r"((a)[3]), "r"(b0), "r"(b1))

__global__ __launch_bounds__(256, 2)
void mma_gemm(const float* __restrict__ b1, const float* __restrict__ w2) {
    const int tid  = threadIdx.x;
    const int wid  = tid >> 5, lane = tid & 31;
    const int mw   = wid >> 2;                 // 0..1  (64-row band)
    const int nw   = wid & 3;                  // 0..3  (32-col band)
    const int bm   = blockIdx.y * BM;
    const int bn   = blockIdx.x * BN;

    __shared__ float w2s[E_DIM][BN];           // 4 KB static
    for (int i = tid; i < E_DIM * BN; i += 256)
        w2s[i >> 7][i & 127] = w2[(i >> 7) * H2_DIM + bn + (i & 127)];

    const uint32_t sbase = smem_u32(dsm);

    const int crow = tid >> 1;
    const int cbyt = (tid & 1) * 32;
    const size_t gaoff = ((size_t)(bm + crow) * H_DIM) * 2 + cbyt;
    const size_t gboff = ((size_t)(bn + crow) * H_DIM) * 2 + cbyt;
    const char* pAh = (const char*)g_ahi + gaoff;
    const char* pAl = (const char*)g_alo + gaoff;
    const char* pBh = (const char*)g_whi + gboff;
    const char* pBl = (const char*)g_wlo + gboff;
    const uint32_t sdst2 = sbase + crow * ROWB + cbyt;

    const int a_off = ((lane & 7) + ((lane & 8) ? 8 : 0)) * ROWB + ((lane & 16) ? 16 : 0);
    const int b_off = ((lane & 7) + ((lane & 16) ? 8 : 0)) * ROWB + ((lane & 8) ? 16 : 0);
    const uint32_t aBandA = (uint32_t)(mw * 64) * ROWB;
    const uint32_t aBandB = (uint32_t)(nw * 32) * ROWB;

    float accf[4][4][4];
    #pragma unroll
    for (int i = 0; i < 4; i++)
        #pragma unroll
        for (int j = 0; j < 4; j++)
            #pragma unroll
            for (int q = 0; q < 4; q++) accf[i][j][q] = 0.f;

    const int NKT = H_DIM / BK;   // 64

    // prologue: fill stage 0
    {
        const uint32_t sd = sdst2;
        CP16(sd,                 pAh); CP16(sd + 16,                 pAh + 16);
        CP16(sd + BUF_BYTES,     pAl); CP16(sd + BUF_BYTES + 16,     pAl + 16);
        CP16(sd + 2 * BUF_BYTES, pBh); CP16(sd + 2 * BUF_BYTES + 16, pBh + 16);
        CP16(sd + 3 * BUF_BYTES, pBl); CP16(sd + 3 * BUF_BYTES + 16, pBl + 16);
        CP_COMMIT();
    }

    for (int kt = 0; kt < NKT; kt++) {
        const int ft = kt + 1;
        if (ft < NKT) {
            const uint32_t sd = sdst2 + (ft & 1) * STAGE_BYTES;
            const size_t ko = (size_t)ft * BK * 2;
            CP16(sd,                 pAh + ko); CP16(sd + 16,                 pAh + ko + 16);
            CP16(sd + BUF_BYTES,     pAl + ko); CP16(sd + BUF_BYTES + 16,     pAl + ko + 16);
            CP16(sd + 2 * BUF_BYTES, pBh + ko); CP16(sd + 2 * BUF_BYTES + 16, pBh + ko + 16);
            CP16(sd + 3 * BUF_BYTES, pBl + ko); CP16(sd + 3 * BUF_BYTES + 16, pBl + ko + 16);
        }
        CP_COMMIT();
        CP_WAIT1();
        __syncthreads();

        const uint32_t st = sbase + (kt & 1) * STAGE_BYTES;
        const uint32_t aH = st + aBandA + a_off;
        const uint32_t aL = st + BUF_BYTES + aBandA + a_off;
        const uint32_t bH = st + 2 * BUF_BYTES + aBandB + b_off;
        const uint32_t bL = st + 3 * BUF_BYTES + aBandB + b_off;

        #pragma unroll
        for (int kk = 0; kk < 2; kk++) {
            const int kb = kk * 32;
            uint32_t a[4][4], bh[8], bl[8];
            LDSM4(&bh[0], bH + kb);
            LDSM4(&bh[4], bH + 16 * ROWB + kb);
            LDSM4(&bl[0], bL + kb);
            LDSM4(&bl[4], bL + 16 * ROWB + kb);
            #pragma unroll
            for (int mt = 0; mt < 4; mt++)
                LDSM4(a[mt], aH + mt * 16 * ROWB + kb);
            #pragma unroll
            for (int mt = 0; mt < 4; mt++)
                #pragma unroll
                for (int nt = 0; nt < 4; nt++)
                    MMA16816(accf[mt][nt], a[mt], bh[nt * 2], bh[nt * 2 + 1]);
            #pragma unroll
            for (int mt = 0; mt < 4; mt++)
                #pragma unroll
                for (int nt = 0; nt < 4; nt++)
                    MMA16816(accf[mt][nt], a[mt], bl[nt * 2], bl[nt * 2 + 1]);
            #pragma unroll
            for (int mt = 0; mt < 4; mt++)
                LDSM4(a[mt], aL + mt * 16 * ROWB + kb);
            #pragma unroll
            for (int mt = 0; mt < 4; mt++)
                #pragma unroll
                for (int nt = 0; nt < 4; nt++)
                    MMA16816(accf[mt][nt], a[mt], bh[nt * 2], bh[nt * 2 + 1]);
        }
        __syncthreads();
    }

    // ---- fused epilogue: bias + exact GELU + per-CTA partial GEMM2 ----
    float* stage = (float*)dsm;
    const int slot = nw * 4 + (lane & 3);
    #pragma unroll
    for (int mt = 0; mt < 4; mt++) {
        #pragma unroll
        for (int half = 0; half < 2; half++) {
            const int rl = mw * 64 + mt * 16 + (lane >> 2) + half * 8;  // local row
            float part[E_DIM] = {0.f, 0.f, 0.f, 0.f, 0.f, 0.f, 0.f, 0.f};
            #pragma unroll
            for (int nt = 0; nt < 4; nt++) {
                const int cl = nw * 32 + nt * 8 + (lane & 3) * 2;
                float v0 = gelu_exact(accf[mt][nt][half * 2 + 0] + b1[bn + cl]);
                float v1 = gelu_exact(accf[mt][nt][half * 2 + 1] + b1[bn + cl + 1]);
                #pragma unroll
                for (int e = 0; e < E_DIM; e++)
                    part[e] += v0 * w2s[e][cl] + v1 * w2s[e][cl + 1];
            }
            #pragma unroll
            for (int e = 0; e < E_DIM; e++)
                stage[(rl * E_DIM + e) * 16 + slot] = part[e];
        }
    }
    __syncthreads();

    for (int p = tid; p < BM * E_DIM; p += 256) {
        const float* sp = stage + p * 16;
        float s = 0.f;
        #pragma unroll
        for (int i = 0; i < 16; i++) s += sp[i];
        g_lpart[blockIdx.x][bm + (p >> 3)][p & 7] = s;
    }
}

// ---------------- K3: fused sum-partials -> ew + ambiguity flagging ----------------
__global__ __launch_bounds__(256)
void ew_flag(const float* __restrict__ b2, float* __restrict__ ew, int N) {
    int t = blockIdx.x * 256 + threadIdx.x;
    if (t >= N) return;
    float o[E_DIM];
    #pragma unroll
    for (int e = 0; e < E_DIM; e++) o[e] = __ldg(b2 + e);
    #pragma unroll
    for (int bnp = 0; bnp < 8; bnp++) {
        const float4* lp = (const float4*)&g_lpart[bnp][t][0];
        float4 p0 = lp[0], p1 = lp[1];
        o[0] += p0.x; o[1] += p0.y; o[2] += p0.z; o[3] += p0.w;
        o[4] += p1.x; o[5] += p1.y; o[6] += p1.z; o[7] += p1.w;
    }
    #pragma unroll
    for (int e = 0; e < E_DIM; e++) {
        float v = o[e] / 0.7f;
        o[e] = fminf(fmaxf(v, -50.0f), 50.0f);
    }
    float4* dst = (float4*)(ew + (size_t)t * E_DIM);
    dst[0] = *(float4*)&o[0];
    dst[1] = *(float4*)&o[4];

    // flag ambiguous top-2 boundary straight from registers
    float m1 = -3.4e38f, m2 = -3.4e38f, m3 = -3.4e38f;
    #pragma unroll
    for (int i = 0; i < 8; i++) {
        float xv = o[i];
        if (xv > m1)      { m3 = m2; m2 = m1; m1 = xv; }
        else if (xv > m2) { m3 = m2; m2 = xv; }
        else if (xv > m3) { m3 = xv; }
    }
    if (m2 - m3 < GAP_DELTA) {
        int idx = atomicAdd(&g_count, 1);
        if (idx < MAX_FLAG) g_flagged[idx] = t;
    }
}

// ---------------- K4: exact fp32 recompute, 8 tokens per block (shared w1 reads) ----
// dynamic smem: a[8][H_DIM] (64 KB) + hrow[8][H2_DIM] (32 KB) = 96 KB
#define PATCH_SMEM (PATCH_BATCH * (H_DIM + H2_DIM) * 4)
__global__ __launch_bounds__(256)
void patch_tokens(const float* __restrict__ x, const float* __restrict__ lnw,
                  const float* __restrict__ lnb, const float* __restrict__ w1,
                  const float* __restrict__ b1, const float* __restrict__ w2,
                  const float* __restrict__ b2, float* __restrict__ ew) {
    int cnt = g_count; if (cnt > MAX_FLAG) cnt = MAX_FLAG;
    int base = blockIdx.x * PATCH_BATCH;
    if (base >= cnt) return;
    int ntk = cnt - base; if (ntk > PATCH_BATCH) ntk = PATCH_BATCH;

    extern __shared__ float psm[];
    float (*a)[H_DIM]    = (float(*)[H_DIM])psm;
    float (*hrow)[H2_DIM] = (float(*)[H2_DIM])(psm + PATCH_BATCH * H_DIM);
    __shared__ int stok[PATCH_BATCH];
    if (threadIdx.x < PATCH_BATCH)
        stok[threadIdx.x] = g_flagged[base + ((int)threadIdx.x < ntk ? threadIdx.x : 0)];
    __syncthreads();

    for (int i = 0; i < ntk; i++) {
        int t = stok[i];
        float mu = g_mu[t], rs = g_rs[t];
        const float* xr = x + (size_t)t * H_DIM;
        for (int k = threadIdx.x; k < H_DIM; k += 256)
            a[i][k] = (xr[k] - mu) * rs * lnw[k] + lnb[k];
    }
    __syncthreads();

    for (int j = threadIdx.x; j < H2_DIM; j += 256) {
        const float* wr = w1 + (size_t)j * H_DIM;
        float sacc[PATCH_BATCH];
        #pragma unroll
        for (int i = 0; i < PATCH_BATCH; i++) sacc[i] = 0.f;
        #pragma unroll 2
        for (int k = 0; k < H_DIM; k += 4) {
            float4 wv = *(const float4*)(wr + k);
            #pragma unroll
            for (int i = 0; i < PATCH_BATCH; i++) {
                if (i < ntk)
                    sacc[i] += a[i][k] * wv.x + a[i][k+1] * wv.y
                             + a[i][k+2] * wv.z + a[i][k+3] * wv.w;
            }
        }
        float bj = b1[j];
        #pragma unroll
        for (int i = 0; i < PATCH_BATCH; i++)
            if (i < ntk) hrow[i][j] = gelu_exact(sacc[i] + bj);
    }
    __syncthreads();

    int wid = threadIdx.x >> 5, lane = threadIdx.x & 31;
    const float* w2r = w2 + wid * H2_DIM;
    for (int i = 0; i < ntk; i++) {
        float s = 0.f;
        for (int k = lane * 4; k < H2_DIM; k += 128) {
            float4 wv = *(const float4*)(w2r + k);
            s += hrow[i][k] * wv.x + hrow[i][k+1] * wv.y
               + hrow[i][k+2] * wv.z + hrow[i][k+3] * wv.w;
        }
        #pragma unroll
        for (int o = 16; o; o >>= 1) s += __shfl_xor_sync(0xffffffffu, s, o);
        if (lane == 0) {
            float v = (s + b2[wid]) / 0.7f;
            v = fminf(fmaxf(v, -50.0f), 50.0f);
            ew[(size_t)stok[i] * E_DIM + wid] = v;
        }
    }
}

// ---------------- K5: fused top-2/softmax/masks + per-expert block sums ----------------
__global__ __launch_bounds__(256)
void topk_esum(const float* __restrict__ ew, float* __restrict__ mout, int N) {
    __shared__ float spre[256][E_DIM];
    int t = blockIdx.x * 256 + threadIdx.x;

    float4 va = ((const float4*)ew)[t * 2];
    float4 vb = ((const float4*)ew)[t * 2 + 1];
    float v[8] = { va.x, va.y, va.z, va.w, vb.x, vb.y, vb.z, vb.w };
    int i1 = 0; float m1 = v[0];
    #pragma unroll
    for (int i = 1; i < 8; i++) if (v[i] > m1) { m1 = v[i]; i1 = i; }
    int i2 = -1; float m2 = -3.4e38f;
    #pragma unroll
    for (int i = 0; i < 8; i++) if (i != i1 && v[i] > m2) { m2 = v[i]; i2 = i; }
    float e2 = expf(m2 - m1);
    float denom = 1.0f + e2;
    float p1 = 1.0f / denom, p2 = e2 / denom;
    float inv = 1.0f / fmaxf(p1 + p2, 1e-6f);
    float nrm[8];
    #pragma unroll
    for (int i = 0; i < 8; i++) {
        float w = (i == i1) ? p1 : ((i == i2) ? p2 : 0.0f);
        spre[threadIdx.x][i] = w;
        nrm[i] = w * inv;
    }
    float* mo = mout + (size_t)t * 8;
    ((float4*)mo)[0] = *(float4*)&nrm[0];
    ((float4*)mo)[1] = *(float4*)&nrm[4];
    __syncthreads();

    // per-expert deterministic block sum: warp e sums tokens lane+32*i, i ascending
    int wid = threadIdx.x >> 5, lane = threadIdx.x & 31;
    float s = 0.f;
    #pragma unroll
    for (int i = 0; i < 8; i++)
        s += spre[lane + i * 32][wid];
    #pragma unroll
    for (int o = 16; o; o >>= 1) s += __shfl_xor_sync(0xffffffffu, s, o);
    if (lane == 0) g_psum[blockIdx.x * E_DIM + wid] = s;
}

// ---------------- K6: usage + KL loss ----------------
__global__ void finalize(float* __restrict__ loss_out, float* __restrict__ usage_out, int N) {
    __shared__ float esum[E_DIM];
    int e = threadIdx.x;
    if (e < E_DIM) {
        float s = 0.f;
        int nb = N / 256;
        for (int b = 0; b < nb; b++) s += g_psum[b * E_DIM + e];
        esum[e] = s;
    }
    __syncthreads();
    if (threadIdx.x == 0) {
        float total = 0.f;
        #pragma unroll
        for (int i = 0; i < 8; i++) total += esum[i];
        float inv = 1.0f / fmaxf(total, 1e-6f);
        const float target = 1.0f / 8.0f;
        float lt = logf(target);
        float kl = 0.f;
        #pragma unroll
        for (int i = 0; i < 8; i++) {
            float u = esum[i] * inv;
            usage_out[i] = u;
            kl += target * (lt - logf(fmaxf(u, 1e-6f)));
        }
        loss_out[0] = 0.01f * (kl / 8.0f);
    }
}

// ---------------- launch ----------------
extern "C" void kernel_launch(void* const* d_in, const int* in_sizes, int n_in,
                              void* d_out, int out_size) {
    const float* x   = (const float*)d_in[0];
    const float* lnw = (const float*)d_in[1];
    const float* lnb = (const float*)d_in[2];
    const float* w1  = (const float*)d_in[3];
    const float* b1  = (const float*)d_in[4];
    const float* w2  = (const float*)d_in[5];
    const float* b2  = (const float*)d_in[6];

    const int N = N_TOK;
    float* out       = (float*)d_out;
    float* ew        = out;                       // [N,8]
    float* masks_out = out + (size_t)N * 8;       // [N,8]
    float* loss_out  = out + (size_t)2 * N * 8;   // [1]
    float* usage_out = loss_out + 1;              // [8]

    cudaFuncSetAttribute(mma_gemm, cudaFuncAttributeMaxDynamicSharedMemorySize, GSMEM);
    cudaFuncSetAttribute(patch_tokens, cudaFuncAttributeMaxDynamicSharedMemorySize, PATCH_SMEM);

    prep<<<N + WSPLIT_BLOCKS, 256>>>(x, lnw, lnb, w1);
    mma_gemm<<<dim3(H2_DIM / BN, N_TOK / BM), 256, GSMEM>>>(b1, w2);
    ew_flag<<<N / 256, 256>>>(b2, ew, N);
    patch_tokens<<<MAX_FLAG / PATCH_BATCH, 256, PATCH_SMEM>>>(x, lnw, lnb, w1, b1, w2, b2, ew);
    topk_esum<<<N / 256, 256>>>(ew, masks_out, N);
    finalize<<<1, 64>>>(loss_out, usage_out, N);
    (void)n_in; (void)out_size; (void)in_sizes;
}

// round 15
// speedup vs baseline: 1.1185x; 1.1185x over previous
#include <cuda_runtime.h>
#include <cuda_bf16.h>
#include <cstdint>
#include <math.h>

// AttentiveRouter: N=32768 tokens, H=2048, H2=1024, E=8, top-2
#define N_TOK  32768
#define H_DIM  2048
#define H2_DIM 1024
#define E_DIM  8
#define GAP_DELTA 2e-3f
#define MAX_FLAG 4096
#define WSPLIT_BLOCKS 264

// ---------------- scratch (static device globals) ----------------
__device__ __nv_bfloat16 g_ahi[(size_t)N_TOK * H_DIM];   // 134 MB
__device__ __nv_bfloat16 g_alo[(size_t)N_TOK * H_DIM];   // 134 MB
__device__ __nv_bfloat16 g_whi[(size_t)H2_DIM * H_DIM];  // 4 MB
__device__ __nv_bfloat16 g_wlo[(size_t)H2_DIM * H_DIM];  // 4 MB
__device__ float g_lpart[8][N_TOK][E_DIM];               // per-bn partial logits, 8 MB
__device__ float g_mu[N_TOK];
__device__ float g_rs[N_TOK];
__device__ float g_psum[(N_TOK / 256) * E_DIM];
__device__ int   g_flagged[MAX_FLAG];
__device__ int   g_count;

__device__ __forceinline__ float gelu_exact(float v) {
    return 0.5f * v * (1.0f + erff(v * 0.70710678118654752440f));
}

// ---------------- K1: fused LayerNorm+split (rows) AND w1 split (tail blocks) ----------------
__global__ __launch_bounds__(256)
void prep(const float* __restrict__ x, const float* __restrict__ lnw,
          const float* __restrict__ lnb, const float* __restrict__ w1) {
    if ((int)blockIdx.x >= N_TOK) {
        // ---- w1 hi/lo split (grid-stride over WSPLIT_BLOCKS tail blocks) ----
        int wb = blockIdx.x - N_TOK;
        if (wb == 0 && threadIdx.x == 0) g_count = 0;
        const float4* src = (const float4*)w1;
        __nv_bfloat162* hi2 = (__nv_bfloat162*)g_whi;
        __nv_bfloat162* lo2 = (__nv_bfloat162*)g_wlo;
        int total = H2_DIM * H_DIM / 4;
        for (int i = wb * 256 + threadIdx.x; i < total; i += WSPLIT_BLOCKS * 256) {
            float4 v = src[i];
            __nv_bfloat162 h0 = __floats2bfloat162_rn(v.x, v.y);
            __nv_bfloat162 h1 = __floats2bfloat162_rn(v.z, v.w);
            __nv_bfloat162 l0 = __floats2bfloat162_rn(v.x - __bfloat162float(h0.x),
                                                      v.y - __bfloat162float(h0.y));
            __nv_bfloat162 l1 = __floats2bfloat162_rn(v.z - __bfloat162float(h1.x),
                                                      v.w - __bfloat162float(h1.y));
            hi2[i * 2 + 0] = h0; hi2[i * 2 + 1] = h1;
            lo2[i * 2 + 0] = l0; lo2[i * 2 + 1] = l1;
        }
        return;
    }

    // ---- LayerNorm stats + bf16 hi/lo split for one token row ----
    int row = blockIdx.x;
    const float4* xr = (const float4*)(x + (size_t)row * H_DIM);
    float4 v0 = xr[threadIdx.x];
    float4 v1 = xr[threadIdx.x + 256];
    float s  = v0.x + v0.y + v0.z + v0.w + v1.x + v1.y + v1.z + v1.w;
    float s2 = v0.x*v0.x + v0.y*v0.y + v0.z*v0.z + v0.w*v0.w
             + v1.x*v1.x + v1.y*v1.y + v1.z*v1.z + v1.w*v1.w;
    #pragma unroll
    for (int o = 16; o; o >>= 1) {
        s  += __shfl_xor_sync(0xffffffffu, s, o);
        s2 += __shfl_xor_sync(0xffffffffu, s2, o);
    }
    __shared__ float sh[8], sh2[8], smu, srs;
    int w = threadIdx.x >> 5, l = threadIdx.x & 31;
    if (l == 0) { sh[w] = s; sh2[w] = s2; }
    __syncthreads();
    if (threadIdx.x == 0) {
        float ts = 0.f, ts2 = 0.f;
        #pragma unroll
        for (int i = 0; i < 8; i++) { ts += sh[i]; ts2 += sh2[i]; }
        float mu  = ts / (float)H_DIM;
        float var = ts2 / (float)H_DIM - mu * mu;
        smu = mu; srs = rsqrtf(var + 1e-5f);
        g_mu[row] = mu; g_rs[row] = srs;
    }
    __syncthreads();
    float mu = smu, rs = srs;

    const float4* wr = (const float4*)lnw;
    const float4* br = (const float4*)lnb;
    __nv_bfloat162* hi2 = (__nv_bfloat162*)(g_ahi + (size_t)row * H_DIM);
    __nv_bfloat162* lo2 = (__nv_bfloat162*)(g_alo + (size_t)row * H_DIM);

    #pragma unroll
    for (int half = 0; half < 2; half++) {
        int qi = threadIdx.x + half * 256;
        float4 xv = half ? v1 : v0;
        float4 wv = wr[qi];
        float4 bv = br[qi];
        float o0 = (xv.x - mu) * rs * wv.x + bv.x;
        float o1 = (xv.y - mu) * rs * wv.y + bv.y;
        float o2 = (xv.z - mu) * rs * wv.z + bv.z;
        float o3 = (xv.w - mu) * rs * wv.w + bv.w;
        __nv_bfloat162 h0 = __floats2bfloat162_rn(o0, o1);
        __nv_bfloat162 h1 = __floats2bfloat162_rn(o2, o3);
        __nv_bfloat162 l0 = __floats2bfloat162_rn(o0 - __bfloat162float(h0.x),
                                                  o1 - __bfloat162float(h0.y));
        __nv_bfloat162 l1 = __floats2bfloat162_rn(o2 - __bfloat162float(h1.x),
                                                  o3 - __bfloat162float(h1.y));
        hi2[qi * 2 + 0] = h0; hi2[qi * 2 + 1] = h1;
        lo2[qi * 2 + 0] = l0; lo2[qi * 2 + 1] = l1;
    }
}

// ---------------- K2: mma.sync bf16x3 GEMM1 + fused bias/GELU/GEMM2-partial ----------------
// (R7-proven layout: 80B-padded smem rows, 2-stage cp.async pipeline)
#define BM 128
#define BN 128
#define BK 32
#define ROWB 80                        // padded smem row bytes (32 bf16 = 64B data)
#define BUF_BYTES (128 * ROWB)         // 10240 per operand buffer
#define STAGE_BYTES (4 * BUF_BYTES)    // Ahi | Alo | Bhi | Blo
#define GSMEM (2 * STAGE_BYTES)        // 81920 -> 2 CTAs/SM

extern __shared__ __align__(128) char dsm[];

__device__ __forceinline__ uint32_t smem_u32(const void* p) {
    uint32_t a;
    asm("{ .reg .u64 t; cvta.to.shared.u64 t, %1; cvt.u32.u64 %0, t; }" : "=r"(a) : "l"(p));
    return a;
}
#define CP16(dst, src) \
    asm volatile("cp.async.cg.shared.global [%0], [%1], 16;" :: "r"(dst), "l"(src))
#define CP_COMMIT() asm volatile("cp.async.commit_group;" ::: "memory")
#define CP_WAIT1()  asm volatile("cp.async.wait_group 1;" ::: "memory")

#define LDSM4(r, addr)                                                        \
    asm volatile("ldmatrix.sync.aligned.m8n8.x4.shared.b16 {%0,%1,%2,%3}, [%4];" \
        : "=r"((r)[0]), "=r"((r)[1]), "=r"((r)[2]), "=r"((r)[3]) : "r"(addr))

#define MMA16816(d, a, b0, b1)                                                \
    asm volatile("mma.sync.aligned.m16n8k16.row.col.f32.bf16.bf16.f32 "       \
        "{%0,%1,%2,%3},{%4,%5,%6,%7},{%8,%9},{%0,%1,%2,%3};"                  \
        : "+f"((d)[0]), "+f"((d)[1]), "+f"((d)[2]), "+f"((d)[3])              \
        : "r"((a)[0]), "r"((a)[1]), "r"((a)[2]), "r"((a)[3]), "r"(b0), "r"(b1))

__global__ __launch_bounds__(256, 2)
void mma_gemm(const float* __restrict__ b1, const float* __restrict__ w2) {
    const int tid  = threadIdx.x;
    const int wid  = tid >> 5, lane = tid & 31;
    const int mw   = wid >> 2;                 // 0..1  (64-row band)
    const int nw   = wid & 3;                  // 0..3  (32-col band)
    const int bm   = blockIdx.y * BM;
    const int bn   = blockIdx.x * BN;

    __shared__ float w2s[E_DIM][BN];           // 4 KB static
    for (int i = tid; i < E_DIM * BN; i += 256)
        w2s[i >> 7][i & 127] = w2[(i >> 7) * H2_DIM + bn + (i & 127)];

    const uint32_t sbase = smem_u32(dsm);

    const int crow = tid >> 1;
    const int cbyt = (tid & 1) * 32;
    const size_t gaoff = ((size_t)(bm + crow) * H_DIM) * 2 + cbyt;
    const size_t gboff = ((size_t)(bn + crow) * H_DIM) * 2 + cbyt;
    const char* pAh = (const char*)g_ahi + gaoff;
    const char* pAl = (const char*)g_alo + gaoff;
    const char* pBh = (const char*)g_whi + gboff;
    const char* pBl = (const char*)g_wlo + gboff;
    const uint32_t sdst2 = sbase + crow * ROWB + cbyt;

    const int a_off = ((lane & 7) + ((lane & 8) ? 8 : 0)) * ROWB + ((lane & 16) ? 16 : 0);
    const int b_off = ((lane & 7) + ((lane & 16) ? 8 : 0)) * ROWB + ((lane & 8) ? 16 : 0);
    const uint32_t aBandA = (uint32_t)(mw * 64) * ROWB;
    const uint32_t aBandB = (uint32_t)(nw * 32) * ROWB;

    float accf[4][4][4];
    #pragma unroll
    for (int i = 0; i < 4; i++)
        #pragma unroll
        for (int j = 0; j < 4; j++)
            #pragma unroll
            for (int q = 0; q < 4; q++) accf[i][j][q] = 0.f;

    const int NKT = H_DIM / BK;   // 64

    // prologue: fill stage 0
    {
        const uint32_t sd = sdst2;
        CP16(sd,                 pAh); CP16(sd + 16,                 pAh + 16);
        CP16(sd + BUF_BYTES,     pAl); CP16(sd + BUF_BYTES + 16,     pAl + 16);
        CP16(sd + 2 * BUF_BYTES, pBh); CP16(sd + 2 * BUF_BYTES + 16, pBh + 16);
        CP16(sd + 3 * BUF_BYTES, pBl); CP16(sd + 3 * BUF_BYTES + 16, pBl + 16);
        CP_COMMIT();
    }

    for (int kt = 0; kt < NKT; kt++) {
        const int ft = kt + 1;
        if (ft < NKT) {
            const uint32_t sd = sdst2 + (ft & 1) * STAGE_BYTES;
            const size_t ko = (size_t)ft * BK * 2;
            CP16(sd,                 pAh + ko); CP16(sd + 16,                 pAh + ko + 16);
            CP16(sd + BUF_BYTES,     pAl + ko); CP16(sd + BUF_BYTES + 16,     pAl + ko + 16);
            CP16(sd + 2 * BUF_BYTES, pBh + ko); CP16(sd + 2 * BUF_BYTES + 16, pBh + ko + 16);
            CP16(sd + 3 * BUF_BYTES, pBl + ko); CP16(sd + 3 * BUF_BYTES + 16, pBl + ko + 16);
        }
        CP_COMMIT();
        CP_WAIT1();
        __syncthreads();

        const uint32_t st = sbase + (kt & 1) * STAGE_BYTES;
        const uint32_t aH = st + aBandA + a_off;
        const uint32_t aL = st + BUF_BYTES + aBandA + a_off;
        const uint32_t bH = st + 2 * BUF_BYTES + aBandB + b_off;
        const uint32_t bL = st + 3 * BUF_BYTES + aBandB + b_off;

        #pragma unroll
        for (int kk = 0; kk < 2; kk++) {
            const int kb = kk * 32;
            uint32_t a[4][4], bh[8], bl[8];
            LDSM4(&bh[0], bH + kb);
            LDSM4(&bh[4], bH + 16 * ROWB + kb);
            LDSM4(&bl[0], bL + kb);
            LDSM4(&bl[4], bL + 16 * ROWB + kb);
            #pragma unroll
            for (int mt = 0; mt < 4; mt++)
                LDSM4(a[mt], aH + mt * 16 * ROWB + kb);
            #pragma unroll
            for (int mt = 0; mt < 4; mt++)
                #pragma unroll
                for (int nt = 0; nt < 4; nt++)
                    MMA16816(accf[mt][nt], a[mt], bh[nt * 2], bh[nt * 2 + 1]);
            #pragma unroll
            for (int mt = 0; mt < 4; mt++)
                #pragma unroll
                for (int nt = 0; nt < 4; nt++)
                    MMA16816(accf[mt][nt], a[mt], bl[nt * 2], bl[nt * 2 + 1]);
            #pragma unroll
            for (int mt = 0; mt < 4; mt++)
                LDSM4(a[mt], aL + mt * 16 * ROWB + kb);
            #pragma unroll
            for (int mt = 0; mt < 4; mt++)
                #pragma unroll
                for (int nt = 0; nt < 4; nt++)
                    MMA16816(accf[mt][nt], a[mt], bh[nt * 2], bh[nt * 2 + 1]);
        }
        __syncthreads();
    }

    // ---- fused epilogue: bias + exact GELU + per-CTA partial GEMM2 ----
    float* stage = (float*)dsm;
    const int slot = nw * 4 + (lane & 3);
    #pragma unroll
    for (int mt = 0; mt < 4; mt++) {
        #pragma unroll
        for (int half = 0; half < 2; half++) {
            const int rl = mw * 64 + mt * 16 + (lane >> 2) + half * 8;  // local row
            float part[E_DIM] = {0.f, 0.f, 0.f, 0.f, 0.f, 0.f, 0.f, 0.f};
            #pragma unroll
            for (int nt = 0; nt < 4; nt++) {
                const int cl = nw * 32 + nt * 8 + (lane & 3) * 2;
                float v0 = gelu_exact(accf[mt][nt][half * 2 + 0] + b1[bn + cl]);
                float v1 = gelu_exact(accf[mt][nt][half * 2 + 1] + b1[bn + cl + 1]);
                #pragma unroll
                for (int e = 0; e < E_DIM; e++)
                    part[e] += v0 * w2s[e][cl] + v1 * w2s[e][cl + 1];
            }
            #pragma unroll
            for (int e = 0; e < E_DIM; e++)
                stage[(rl * E_DIM + e) * 16 + slot] = part[e];
        }
    }
    __syncthreads();

    for (int p = tid; p < BM * E_DIM; p += 256) {
        const float* sp = stage + p * 16;
        float s = 0.f;
        #pragma unroll
        for (int i = 0; i < 16; i++) s += sp[i];
        g_lpart[blockIdx.x][bm + (p >> 3)][p & 7] = s;
    }
}

// ---------------- K3: fused sum-partials -> ew + ambiguity flagging ----------------
__global__ __launch_bounds__(256)
void ew_flag(const float* __restrict__ b2, float* __restrict__ ew, int N) {
    int t = blockIdx.x * 256 + threadIdx.x;
    if (t >= N) return;
    float o[E_DIM];
    #pragma unroll
    for (int e = 0; e < E_DIM; e++) o[e] = __ldg(b2 + e);
    #pragma unroll
    for (int bnp = 0; bnp < 8; bnp++) {
        const float4* lp = (const float4*)&g_lpart[bnp][t][0];
        float4 p0 = lp[0], p1 = lp[1];
        o[0] += p0.x; o[1] += p0.y; o[2] += p0.z; o[3] += p0.w;
        o[4] += p1.x; o[5] += p1.y; o[6] += p1.z; o[7] += p1.w;
    }
    #pragma unroll
    for (int e = 0; e < E_DIM; e++) {
        float v = o[e] / 0.7f;
        o[e] = fminf(fmaxf(v, -50.0f), 50.0f);
    }
    float4* dst = (float4*)(ew + (size_t)t * E_DIM);
    dst[0] = *(float4*)&o[0];
    dst[1] = *(float4*)&o[4];

    // flag ambiguous top-2 boundary straight from registers
    float m1 = -3.4e38f, m2 = -3.4e38f, m3 = -3.4e38f;
    #pragma unroll
    for (int i = 0; i < 8; i++) {
        float xv = o[i];
        if (xv > m1)      { m3 = m2; m2 = m1; m1 = xv; }
        else if (xv > m2) { m3 = m2; m2 = xv; }
        else if (xv > m3) { m3 = xv; }
    }
    if (m2 - m3 < GAP_DELTA) {
        int idx = atomicAdd(&g_count, 1);
        if (idx < MAX_FLAG) g_flagged[idx] = t;
    }
}

// ---------------- K4: exact fp32 recompute, 4 tokens per block (R12-proven) ----------
__global__ __launch_bounds__(256)
void patch_tokens(const float* __restrict__ x, const float* __restrict__ lnw,
                  const float* __restrict__ lnb, const float* __restrict__ w1,
                  const float* __restrict__ b1, const float* __restrict__ w2,
                  const float* __restrict__ b2, float* __restrict__ ew) {
    int cnt = g_count; if (cnt > MAX_FLAG) cnt = MAX_FLAG;
    int base = blockIdx.x * 4;
    if (base >= cnt) return;
    int ntk = cnt - base; if (ntk > 4) ntk = 4;

    __shared__ float a[4][H_DIM];       // 32 KB
    __shared__ float hrow[4][H2_DIM];   // 16 KB
    __shared__ int  stok[4];
    if (threadIdx.x < 4)
        stok[threadIdx.x] = g_flagged[base + ((int)threadIdx.x < ntk ? threadIdx.x : 0)];
    __syncthreads();

    for (int i = 0; i < ntk; i++) {
        int t = stok[i];
        float mu = g_mu[t], rs = g_rs[t];
        const float* xr = x + (size_t)t * H_DIM;
        for (int k = threadIdx.x; k < H_DIM; k += 256)
            a[i][k] = (xr[k] - mu) * rs * lnw[k] + lnb[k];
    }
    __syncthreads();

    for (int j = threadIdx.x; j < H2_DIM; j += 256) {
        const float* wr = w1 + (size_t)j * H_DIM;
        float s0 = 0.f, s1 = 0.f, s2 = 0.f, s3 = 0.f;
        #pragma unroll 4
        for (int k = 0; k < H_DIM; k += 4) {
            float4 wv = *(const float4*)(wr + k);
            s0 += a[0][k] * wv.x + a[0][k+1] * wv.y + a[0][k+2] * wv.z + a[0][k+3] * wv.w;
            if (ntk > 1) s1 += a[1][k] * wv.x + a[1][k+1] * wv.y + a[1][k+2] * wv.z + a[1][k+3] * wv.w;
            if (ntk > 2) s2 += a[2][k] * wv.x + a[2][k+1] * wv.y + a[2][k+2] * wv.z + a[2][k+3] * wv.w;
            if (ntk > 3) s3 += a[3][k] * wv.x + a[3][k+1] * wv.y + a[3][k+2] * wv.z + a[3][k+3] * wv.w;
        }
        float bj = b1[j];
        hrow[0][j] = gelu_exact(s0 + bj);
        if (ntk > 1) hrow[1][j] = gelu_exact(s1 + bj);
        if (ntk > 2) hrow[2][j] = gelu_exact(s2 + bj);
        if (ntk > 3) hrow[3][j] = gelu_exact(s3 + bj);
    }
    __syncthreads();

    int wid = threadIdx.x >> 5, lane = threadIdx.x & 31;
    const float* w2r = w2 + wid * H2_DIM;
    for (int i = 0; i < ntk; i++) {
        float s = 0.f;
        for (int k = lane * 4; k < H2_DIM; k += 128) {
            float4 wv = *(const float4*)(w2r + k);
            s += hrow[i][k] * wv.x + hrow[i][k+1] * wv.y
               + hrow[i][k+2] * wv.z + hrow[i][k+3] * wv.w;
        }
        #pragma unroll
        for (int o = 16; o; o >>= 1) s += __shfl_xor_sync(0xffffffffu, s, o);
        if (lane == 0) {
            float v = (s + b2[wid]) / 0.7f;
            v = fminf(fmaxf(v, -50.0f), 50.0f);
            ew[(size_t)stok[i] * E_DIM + wid] = v;
        }
    }
}

// ---------------- K5: fused top-2/softmax/masks + per-expert block sums ----------------
__global__ __launch_bounds__(256)
void topk_esum(const float* __restrict__ ew, float* __restrict__ mout, int N) {
    __shared__ float spre[256][E_DIM];
    int t = blockIdx.x * 256 + threadIdx.x;

    float4 va = ((const float4*)ew)[t * 2];
    float4 vb = ((const float4*)ew)[t * 2 + 1];
    float v[8] = { va.x, va.y, va.z, va.w, vb.x, vb.y, vb.z, vb.w };
    int i1 = 0; float m1 = v[0];
    #pragma unroll
    for (int i = 1; i < 8; i++) if (v[i] > m1) { m1 = v[i]; i1 = i; }
    int i2 = -1; float m2 = -3.4e38f;
    #pragma unroll
    for (int i = 0; i < 8; i++) if (i != i1 && v[i] > m2) { m2 = v[i]; i2 = i; }
    float e2 = expf(m2 - m1);
    float denom = 1.0f + e2;
    float p1 = 1.0f / denom, p2 = e2 / denom;
    float inv = 1.0f / fmaxf(p1 + p2, 1e-6f);
    float nrm[8];
    #pragma unroll
    for (int i = 0; i < 8; i++) {
        float w = (i == i1) ? p1 : ((i == i2) ? p2 : 0.0f);
        spre[threadIdx.x][i] = w;
        nrm[i] = w * inv;
    }
    float* mo = mout + (size_t)t * 8;
    ((float4*)mo)[0] = *(float4*)&nrm[0];
    ((float4*)mo)[1] = *(float4*)&nrm[4];
    __syncthreads();

    // per-expert deterministic block sum: warp e sums tokens lane+32*i, i ascending
    int wid = threadIdx.x >> 5, lane = threadIdx.x & 31;
    float s = 0.f;
    #pragma unroll
    for (int i = 0; i < 8; i++)
        s += spre[lane + i * 32][wid];
    #pragma unroll
    for (int o = 16; o; o >>= 1) s += __shfl_xor_sync(0xffffffffu, s, o);
    if (lane == 0) g_psum[blockIdx.x * E_DIM + wid] = s;
}

// ---------------- K6: usage + KL loss ----------------
__global__ void finalize(float* __restrict__ loss_out, float* __restrict__ usage_out, int N) {
    __shared__ float esum[E_DIM];
    int e = threadIdx.x;
    if (e < E_DIM) {
        float s = 0.f;
        int nb = N / 256;
        for (int b = 0; b < nb; b++) s += g_psum[b * E_DIM + e];
        esum[e] = s;
    }
    __syncthreads();
    if (threadIdx.x == 0) {
        float total = 0.f;
        #pragma unroll
        for (int i = 0; i < 8; i++) total += esum[i];
        float inv = 1.0f / fmaxf(total, 1e-6f);
        const float target = 1.0f / 8.0f;
        float lt = logf(target);
        float kl = 0.f;
        #pragma unroll
        for (int i = 0; i < 8; i++) {
            float u = esum[i] * inv;
            usage_out[i] = u;
            kl += target * (lt - logf(fmaxf(u, 1e-6f)));
        }
        loss_out[0] = 0.01f * (kl / 8.0f);
    }
}

// ---------------- launch ----------------
extern "C" void kernel_launch(void* const* d_in, const int* in_sizes, int n_in,
                              void* d_out, int out_size) {
    const float* x   = (const float*)d_in[0];
    const float* lnw = (const float*)d_in[1];
    const float* lnb = (const float*)d_in[2];
    const float* w1  = (const float*)d_in[3];
    const float* b1  = (const float*)d_in[4];
    const float* w2  = (const float*)d_in[5];
    const float* b2  = (const float*)d_in[6];

    const int N = N_TOK;
    float* out       = (float*)d_out;
    float* ew        = out;                       // [N,8]
    float* masks_out = out + (size_t)N * 8;       // [N,8]
    float* loss_out  = out + (size_t)2 * N * 8;   // [1]
    float* usage_out = loss_out + 1;              // [8]

    cudaFuncSetAttribute(mma_gemm, cudaFuncAttributeMaxDynamicSharedMemorySize, GSMEM);

    prep<<<N + WSPLIT_BLOCKS, 256>>>(x, lnw, lnb, w1);
    mma_gemm<<<dim3(H2_DIM / BN, N_TOK / BM), 256, GSMEM>>>(b1, w2);
    ew_flag<<<N / 256, 256>>>(b2, ew, N);
    patch_tokens<<<MAX_FLAG / 4, 256>>>(x, lnw, lnb, w1, b1, w2, b2, ew);
    topk_esum<<<N / 256, 256>>>(ew, masks_out, N);
    finalize<<<1, 64>>>(loss_out, usage_out, N);
    (void)n_in; (void)out_size; (void)in_sizes;
}